// round 13
// baseline (speedup 1.0000x reference)
#include <cuda_runtime.h>
#include <cuda_fp16.h>

#define NP 50000          // N_PROT
#define ND 5000           // N_DRUG
#define EPP 1600000
#define EPD 200000
#define INP 128           // IN_PROT / IN_DRUG
#define D1 64
#define D2 32
#define OUTD 64

#define NB  196           // 256-wide scan blocks covering NP
#define NBD 20            // 256-wide scan blocks covering ND
#define CSRG 592          // fused CSR kernel grid (148 SMs x 4, co-resident)

// ---------------- scratch (device globals: no allocation allowed) ----------------
__device__ int      g_deg[NP];
__device__ float    g_dinv[NP];
__device__ int      g_bsum[NB];
__device__ int      g_boff[NB];
__device__ int      g_off[NP + 1];    // pp CSR row offsets (by dst protein)
__device__ int      g_pos[NP];
__device__ int      g_er[EPP];        // pp CSR: src index per slot (weights factored out)
__device__ int      g_degd[ND];
__device__ int      g_bsumd[NBD];
__device__ int      g_boffd[NBD];
__device__ int      g_offd[ND + 1];   // pd CSR row offsets (by drug)
__device__ int      g_posd[ND];
__device__ int      g_pdsrc[EPD];     // pd CSR: protein src per slot
__device__ __half   g_h1[NP * D1];    // x_prot @ W1, then scaled in-place: dinv*h1 (fp16)
__device__ __half   g_o1h[NP * D1];   // relu(propagated layer-1) (fp16)
__device__ __half   g_h2[NP * D2];    // dinv * (relu(o1) @ W2) (fp16)
__device__ unsigned g_barcnt = 0;
__device__ volatile unsigned g_bargen = 0;

// ---------------- helpers ----------------
__device__ __forceinline__ void grid_barrier() {
    __syncthreads();
    if (threadIdx.x == 0) {
        unsigned gen = g_bargen;
        __threadfence();
        unsigned t = atomicAdd(&g_barcnt, 1u);
        if (t == CSRG - 1) {
            g_barcnt = 0;
            __threadfence();
            g_bargen = gen + 1;
        } else {
            while (g_bargen == gen) __nanosleep(64);
        }
        __threadfence();
    }
    __syncthreads();
}

// ---------------- fused CSR build (pp by dst-protein AND pd by dst-drug) ----------------
__global__ void __launch_bounds__(256, 4)
k_csr(const int4* __restrict__ src4, const int4* __restrict__ dst4,
      const int* __restrict__ pds, const int* __restrict__ pdd) {
    __shared__ int sh[256];
    __shared__ int wsum[8];
    const int tid = threadIdx.x, b = blockIdx.x;
    const int gid = b * 256 + tid, gsz = CSRG * 256;

    // P0: zero degree arrays
    for (int i = gid; i < NP; i += gsz) g_deg[i] = 0;
    for (int i = gid; i < ND; i += gsz) g_degd[i] = 0;
    grid_barrier();

    // P1: degree histograms
    for (int i = gid; i < EPP / 4; i += gsz) {
        int4 d4 = dst4[i];
        atomicAdd(&g_deg[d4.x], 1); atomicAdd(&g_deg[d4.y], 1);
        atomicAdd(&g_deg[d4.z], 1); atomicAdd(&g_deg[d4.w], 1);
    }
    for (int i = gid; i < EPD; i += gsz) atomicAdd(&g_degd[pdd[i]], 1);
    grid_barrier();

    // P2: per-block sums (pp: blocks [0,NB); pd: blocks [NB, NB+NBD))
    if (b < NB) {
        int i = b * 256 + tid;
        int s = (i < NP) ? g_deg[i] : 0;
#pragma unroll
        for (int o = 16; o > 0; o >>= 1) s += __shfl_down_sync(0xffffffffu, s, o);
        if ((tid & 31) == 0) wsum[tid >> 5] = s;
        __syncthreads();
        if (tid < 8) {
            int w = wsum[tid];
#pragma unroll
            for (int o = 4; o > 0; o >>= 1) w += __shfl_down_sync(0xffu, w, o);
            if (tid == 0) g_bsum[b] = w;
        }
    } else if (b < NB + NBD) {
        int cb = b - NB;
        int i = cb * 256 + tid;
        int s = (i < ND) ? g_degd[i] : 0;
#pragma unroll
        for (int o = 16; o > 0; o >>= 1) s += __shfl_down_sync(0xffffffffu, s, o);
        if ((tid & 31) == 0) wsum[tid >> 5] = s;
        __syncthreads();
        if (tid < 8) {
            int w = wsum[tid];
#pragma unroll
            for (int o = 4; o > 0; o >>= 1) w += __shfl_down_sync(0xffu, w, o);
            if (tid == 0) g_bsumd[cb] = w;
        }
    }
    grid_barrier();

    // P3: block 0 scans pp partials; block 1 scans pd partials
    if (b == 0) {
        int v = (tid < NB) ? g_bsum[tid] : 0;
        sh[tid] = v;
        __syncthreads();
        for (int o = 1; o < 256; o <<= 1) {
            int u = (tid >= o) ? sh[tid - o] : 0;
            __syncthreads();
            sh[tid] += u;
            __syncthreads();
        }
        if (tid < NB) g_boff[tid] = sh[tid] - v;
    } else if (b == 1) {
        int v = (tid < NBD) ? g_bsumd[tid] : 0;
        sh[tid] = v;
        __syncthreads();
        for (int o = 1; o < 256; o <<= 1) {
            int u = (tid >= o) ? sh[tid - o] : 0;
            __syncthreads();
            sh[tid] += u;
            __syncthreads();
        }
        if (tid < NBD) g_boffd[tid] = sh[tid] - v;
    }
    grid_barrier();

    // P4: local exclusive scans
    if (b < NB) {
        int i = b * 256 + tid;
        int v = (i < NP) ? g_deg[i] : 0;
        sh[tid] = v;
        __syncthreads();
        for (int o = 1; o < 256; o <<= 1) {
            int u = (tid >= o) ? sh[tid - o] : 0;
            __syncthreads();
            sh[tid] += u;
            __syncthreads();
        }
        if (i < NP) {
            int off = g_boff[b] + sh[tid] - v;
            g_off[i] = off;
            g_pos[i] = off;
            g_dinv[i] = rsqrtf((float)v + 1.0f);   // +1 = self loop
        }
        if (i == NP - 1) g_off[NP] = EPP;
    } else if (b < NB + NBD) {
        int cb = b - NB;
        int i = cb * 256 + tid;
        int v = (i < ND) ? g_degd[i] : 0;
        sh[tid] = v;
        __syncthreads();
        for (int o = 1; o < 256; o <<= 1) {
            int u = (tid >= o) ? sh[tid - o] : 0;
            __syncthreads();
            sh[tid] += u;
            __syncthreads();
        }
        if (i < ND) {
            int off = g_boffd[cb] + sh[tid] - v;
            g_offd[i] = off;
            g_posd[i] = off;
        }
        if (i == ND - 1) g_offd[ND] = EPD;
    }
    grid_barrier();

    // P5: placement (counting sort); record = bare src index
    for (int i = gid; i < EPP / 4; i += gsz) {
        int4 s4 = src4[i];
        int4 d4 = dst4[i];
        { int p = atomicAdd(&g_pos[d4.x], 1); g_er[p] = s4.x; }
        { int p = atomicAdd(&g_pos[d4.y], 1); g_er[p] = s4.y; }
        { int p = atomicAdd(&g_pos[d4.z], 1); g_er[p] = s4.z; }
        { int p = atomicAdd(&g_pos[d4.w], 1); g_er[p] = s4.w; }
    }
    for (int i = gid; i < EPD; i += gsz) {
        int p = atomicAdd(&g_posd[pdd[i]], 1);
        g_pdsrc[p] = pds[i];
    }
}

// ---------------- GEMM1: Y = X @ W, fp32 in, fp16 out ----------------
template <int K, int M, int KC>
__global__ void __launch_bounds__(256)
k_gemm_h(const float* __restrict__ X, const float* __restrict__ W,
         __half* __restrict__ Y, int N) {
    constexpr int CG  = M / 4;
    constexpr int RG  = 256 / CG;
    constexpr int RPB = RG * 4;
    constexpr int KCP = KC + 2;
    __shared__ float Ws[K * M];
    __shared__ float Xs[RPB][KCP];

    const int tid = threadIdx.x;
    for (int i = tid; i < K * M; i += 256) Ws[i] = W[i];

    const int row0 = blockIdx.x * RPB;
    const int cg = tid % CG, rg = tid / CG;
    const int c0 = cg * 4, r0 = rg * 4;
    float acc[4][4];
#pragma unroll
    for (int j = 0; j < 4; j++)
#pragma unroll
        for (int i = 0; i < 4; i++) acc[j][i] = 0.f;

    for (int kc0 = 0; kc0 < K; kc0 += KC) {
        constexpr int NV = RPB * KC / 4;
#pragma unroll
        for (int v = 0; v < NV / 256; v++) {
            int idx = tid + v * 256;
            int r = idx / (KC / 4), kq = idx % (KC / 4);
            int gr = row0 + r;
            float4 x = make_float4(0.f, 0.f, 0.f, 0.f);
            if (gr < N) x = *(const float4*)&X[(long long)gr * K + kc0 + kq * 4];
            Xs[r][kq * 4 + 0] = x.x; Xs[r][kq * 4 + 1] = x.y;
            Xs[r][kq * 4 + 2] = x.z; Xs[r][kq * 4 + 3] = x.w;
        }
        __syncthreads();
#pragma unroll 4
        for (int k = 0; k < KC; k++) {
            float4 wb = *(const float4*)&Ws[(kc0 + k) * M + c0];
#pragma unroll
            for (int j = 0; j < 4; j++) {
                float xa = Xs[r0 + j][k];
                acc[j][0] = fmaf(xa, wb.x, acc[j][0]);
                acc[j][1] = fmaf(xa, wb.y, acc[j][1]);
                acc[j][2] = fmaf(xa, wb.z, acc[j][2]);
                acc[j][3] = fmaf(xa, wb.w, acc[j][3]);
            }
        }
        __syncthreads();
    }

#pragma unroll
    for (int j = 0; j < 4; j++) {
        int gr = row0 + r0 + j;
        if (gr < N) {
            __half2 p0 = __floats2half2_rn(acc[j][0], acc[j][1]);
            __half2 p1 = __floats2half2_rn(acc[j][2], acc[j][3]);
            uint2 pk;
            pk.x = *(unsigned int*)&p0;
            pk.y = *(unsigned int*)&p1;
            *(uint2*)(Y + (long long)gr * M + c0) = pk;
        }
    }
}

// ---------------- scale: g_h1 *= dinv[row] (in place, 16 halves/thread) ----------------
__global__ void __launch_bounds__(256)
k_scale1() {
    int t = blockIdx.x * blockDim.x + threadIdx.x;
    if (t >= NP * D1 / 16) return;          // 200000 threads
    float d = g_dinv[t >> 2];               // 4 threads per row, same dinv
    uint4* p = (uint4*)g_h1;
    uint4 a = p[2 * t], b = p[2 * t + 1];
    unsigned* va = (unsigned*)&a;
    unsigned* vb = (unsigned*)&b;
#pragma unroll
    for (int i = 0; i < 4; i++) {
        float2 fa = __half22float2(*(__half2*)&va[i]);
        float2 fb = __half22float2(*(__half2*)&vb[i]);
        __half2 ha = __floats2half2_rn(fa.x * d, fa.y * d);
        __half2 hb = __floats2half2_rn(fb.x * d, fb.y * d);
        va[i] = *(unsigned*)&ha;
        vb[i] = *(unsigned*)&hb;
    }
    p[2 * t] = a;
    p[2 * t + 1] = b;
}

// ---------------- GEMM2: Y = Xh @ W scaled by dinv, fp16 in/out ----------------
__global__ void __launch_bounds__(256)
k_gemm2h(const __half* __restrict__ Xh, const float* __restrict__ W,
         __half* __restrict__ Y, int N) {
    constexpr int K = D1, M = D2;
    constexpr int RPB = 128;
    __shared__ float Ws[K * M];
    __shared__ float Xs[RPB][K + 2];

    const int tid = threadIdx.x;
    for (int i = tid; i < K * M; i += 256) Ws[i] = W[i];

    const int row0 = blockIdx.x * RPB;
#pragma unroll
    for (int v = 0; v < 8; v++) {
        int idx = tid + v * 256;
        int r = idx / 16, kq = idx % 16;
        int gr = row0 + r;
        float4 xf = make_float4(0.f, 0.f, 0.f, 0.f);
        if (gr < N) {
            uint2 raw = *(const uint2*)(Xh + (long long)gr * K + kq * 4);
            float2 lo = __half22float2(*(__half2*)&raw.x);
            float2 hi = __half22float2(*(__half2*)&raw.y);
            xf = make_float4(lo.x, lo.y, hi.x, hi.y);
        }
        Xs[r][kq * 4 + 0] = xf.x; Xs[r][kq * 4 + 1] = xf.y;
        Xs[r][kq * 4 + 2] = xf.z; Xs[r][kq * 4 + 3] = xf.w;
    }
    __syncthreads();

    const int cg = tid % 8, rg = tid / 8;
    const int c0 = cg * 4, r0 = rg * 4;
    float acc[4][4];
#pragma unroll
    for (int j = 0; j < 4; j++)
#pragma unroll
        for (int i = 0; i < 4; i++) acc[j][i] = 0.f;
#pragma unroll 4
    for (int k = 0; k < K; k++) {
        float4 wb = *(const float4*)&Ws[k * M + c0];
#pragma unroll
        for (int j = 0; j < 4; j++) {
            float xa = Xs[r0 + j][k];
            acc[j][0] = fmaf(xa, wb.x, acc[j][0]);
            acc[j][1] = fmaf(xa, wb.y, acc[j][1]);
            acc[j][2] = fmaf(xa, wb.z, acc[j][2]);
            acc[j][3] = fmaf(xa, wb.w, acc[j][3]);
        }
    }
#pragma unroll
    for (int j = 0; j < 4; j++) {
        int gr = row0 + r0 + j;
        if (gr < N) {
            float d = g_dinv[gr];       // fuse dinv scaling (ht2 = dinv * h2)
            __half2 p0 = __floats2half2_rn(acc[j][0] * d, acc[j][1] * d);
            __half2 p1 = __floats2half2_rn(acc[j][2] * d, acc[j][3] * d);
            uint2 pk;
            pk.x = *(unsigned int*)&p0;
            pk.y = *(unsigned int*)&p1;
            *(uint2*)(Y + (long long)gr * M + c0) = pk;
        }
    }
}

// ---------------- gather layer1: warp/row, two 16-lane edge groups, 4-deep ----------------
// out[d] = relu(b1 + dinv[d] * (ht1[d] + sum_e ht1[src])), fp16 out
__global__ void __launch_bounds__(256)
k_gather64(const __half* __restrict__ ht, const float* __restrict__ b1,
           __half* __restrict__ out) {
    const int warp = (blockIdx.x * blockDim.x + threadIdx.x) >> 5;
    if (warp >= NP) return;
    const int lane = threadIdx.x & 31;
    const int g = lane >> 4, l = lane & 15;
    const uint2* __restrict__ rows = (const uint2*)ht;   // row stride 16 uint2
    const int beg = g_off[warp], end = g_off[warp + 1];

    float a0 = 0.f, a1 = 0.f, a2 = 0.f, a3 = 0.f;
    int e = beg + g;
    for (; e + 6 < end; e += 8) {               // 4 edges in flight per group
        int s0 = g_er[e],     s1 = g_er[e + 2];
        int s2 = g_er[e + 4], s3 = g_er[e + 6];
        uint2 r0 = rows[s0 * 16 + l];
        uint2 r1 = rows[s1 * 16 + l];
        uint2 r2 = rows[s2 * 16 + l];
        uint2 r3 = rows[s3 * 16 + l];
        float2 l0 = __half22float2(*(__half2*)&r0.x), h0 = __half22float2(*(__half2*)&r0.y);
        float2 l1 = __half22float2(*(__half2*)&r1.x), h1v = __half22float2(*(__half2*)&r1.y);
        float2 l2 = __half22float2(*(__half2*)&r2.x), h2v = __half22float2(*(__half2*)&r2.y);
        float2 l3 = __half22float2(*(__half2*)&r3.x), h3v = __half22float2(*(__half2*)&r3.y);
        a0 += (l0.x + l1.x) + (l2.x + l3.x);
        a1 += (l0.y + l1.y) + (l2.y + l3.y);
        a2 += (h0.x + h1v.x) + (h2v.x + h3v.x);
        a3 += (h0.y + h1v.y) + (h2v.y + h3v.y);
    }
    for (; e < end; e += 2) {
        uint2 r0 = rows[g_er[e] * 16 + l];
        float2 l0 = __half22float2(*(__half2*)&r0.x), h0 = __half22float2(*(__half2*)&r0.y);
        a0 += l0.x; a1 += l0.y; a2 += h0.x; a3 += h0.y;
    }
    if (g == 0) {   // self term once
        uint2 rs = rows[warp * 16 + l];
        float2 ls = __half22float2(*(__half2*)&rs.x), hs = __half22float2(*(__half2*)&rs.y);
        a0 += ls.x; a1 += ls.y; a2 += hs.x; a3 += hs.y;
    }
    a0 += __shfl_xor_sync(0xffffffffu, a0, 16);
    a1 += __shfl_xor_sync(0xffffffffu, a1, 16);
    a2 += __shfl_xor_sync(0xffffffffu, a2, 16);
    a3 += __shfl_xor_sync(0xffffffffu, a3, 16);

    if (g == 0) {
        float d = g_dinv[warp];
        float4 bv = ((const float4*)b1)[l];
        float o0 = fmaxf(fmaf(d, a0, bv.x), 0.f);
        float o1 = fmaxf(fmaf(d, a1, bv.y), 0.f);
        float o2 = fmaxf(fmaf(d, a2, bv.z), 0.f);
        float o3 = fmaxf(fmaf(d, a3, bv.w), 0.f);
        __half2 p0 = __floats2half2_rn(o0, o1);
        __half2 p1 = __floats2half2_rn(o2, o3);
        uint2 pk;
        pk.x = *(unsigned*)&p0;
        pk.y = *(unsigned*)&p1;
        ((uint2*)out)[warp * 16 + l] = pk;
    }
}

// ---------------- gather layer2: warp/row, four 8-lane edge groups, 4-deep; fp32 out ----------------
// out[d] = b2 + dinv[d] * (ht2[d] + sum_e ht2[src])
__global__ void __launch_bounds__(256)
k_gather32(const __half* __restrict__ ht, const float* __restrict__ b2,
           float* __restrict__ out) {
    const int warp = (blockIdx.x * blockDim.x + threadIdx.x) >> 5;
    if (warp >= NP) return;
    const int lane = threadIdx.x & 31;
    const int g = lane >> 3, l = lane & 7;
    const uint2* __restrict__ rows = (const uint2*)ht;   // row stride 8 uint2
    const int beg = g_off[warp], end = g_off[warp + 1];

    float a0 = 0.f, a1 = 0.f, a2 = 0.f, a3 = 0.f;
    int e = beg + g;
    for (; e + 12 < end; e += 16) {             // 4 edges in flight per group
        int s0 = g_er[e],     s1 = g_er[e + 4];
        int s2 = g_er[e + 8], s3 = g_er[e + 12];
        uint2 r0 = rows[s0 * 8 + l];
        uint2 r1 = rows[s1 * 8 + l];
        uint2 r2 = rows[s2 * 8 + l];
        uint2 r3 = rows[s3 * 8 + l];
        float2 l0 = __half22float2(*(__half2*)&r0.x), h0 = __half22float2(*(__half2*)&r0.y);
        float2 l1 = __half22float2(*(__half2*)&r1.x), h1v = __half22float2(*(__half2*)&r1.y);
        float2 l2 = __half22float2(*(__half2*)&r2.x), h2v = __half22float2(*(__half2*)&r2.y);
        float2 l3 = __half22float2(*(__half2*)&r3.x), h3v = __half22float2(*(__half2*)&r3.y);
        a0 += (l0.x + l1.x) + (l2.x + l3.x);
        a1 += (l0.y + l1.y) + (l2.y + l3.y);
        a2 += (h0.x + h1v.x) + (h2v.x + h3v.x);
        a3 += (h0.y + h1v.y) + (h2v.y + h3v.y);
    }
    for (; e < end; e += 4) {
        uint2 r0 = rows[g_er[e] * 8 + l];
        float2 l0 = __half22float2(*(__half2*)&r0.x), h0 = __half22float2(*(__half2*)&r0.y);
        a0 += l0.x; a1 += l0.y; a2 += h0.x; a3 += h0.y;
    }
    if (g == 0) {
        uint2 rs = rows[warp * 8 + l];
        float2 ls = __half22float2(*(__half2*)&rs.x), hs = __half22float2(*(__half2*)&rs.y);
        a0 += ls.x; a1 += ls.y; a2 += hs.x; a3 += hs.y;
    }
#pragma unroll
    for (int o = 8; o <= 16; o <<= 1) {
        a0 += __shfl_xor_sync(0xffffffffu, a0, o);
        a1 += __shfl_xor_sync(0xffffffffu, a1, o);
        a2 += __shfl_xor_sync(0xffffffffu, a2, o);
        a3 += __shfl_xor_sync(0xffffffffu, a3, o);
    }
    if (g == 0) {
        float d = g_dinv[warp];
        float4 bv = ((const float4*)b2)[l];
        float4 ov = make_float4(fmaf(d, a0, bv.x), fmaf(d, a1, bv.y),
                                fmaf(d, a2, bv.z), fmaf(d, a3, bv.w));
        ((float4*)out)[warp * 8 + l] = ov;
    }
}

// ---------------- drug stage: gather-mean over pd CSR, @Wl, + x_drug@Wr + bl ----------------
__global__ void __launch_bounds__(256)
k_drug(const float* __restrict__ h, const float* __restrict__ xd,
       const float* __restrict__ Wl, const float* __restrict__ Wr,
       const float* __restrict__ bl, float* __restrict__ out) {
    __shared__ float Wls[D2 * OUTD];    // 8KB
    __shared__ float Wrs[INP * OUTD];   // 32KB
    __shared__ float Ms[8][D2];         // 1KB
    __shared__ float Xs[8][INP];        // 4KB
    const int tid = threadIdx.x;
    for (int i = tid; i < D2 * OUTD; i += 256) Wls[i] = Wl[i];
    for (int i = tid; i < INP * OUTD; i += 256) Wrs[i] = Wr[i];
    __syncthreads();

    const int w = tid >> 5, lane = tid & 31;
    const int d = blockIdx.x * 8 + w;
    if (d >= ND) return;

    // stage x_drug row (128 floats: each lane a float4)
    {
        float4 xv = ((const float4*)(xd + d * INP))[lane];
        Xs[w][lane * 4 + 0] = xv.x; Xs[w][lane * 4 + 1] = xv.y;
        Xs[w][lane * 4 + 2] = xv.z; Xs[w][lane * 4 + 3] = xv.w;
    }

    // mean over pd neighbors
    const int beg = g_offd[d], end = g_offd[d + 1];
    float sum = 0.f;
    int e = beg;
    for (; e + 1 < end; e += 2) {
        int s0 = g_pdsrc[e], s1 = g_pdsrc[e + 1];
        sum += h[s0 * D2 + lane] + h[s1 * D2 + lane];
    }
    if (e < end) sum += h[g_pdsrc[e] * D2 + lane];
    float cnt = fmaxf((float)(end - beg), 1.0f);
    Ms[w][lane] = sum / cnt;
    __syncwarp();

    float acc_a = bl[lane];
    float acc_b = bl[32 + lane];
#pragma unroll 8
    for (int k = 0; k < INP; k++) {
        float xv = Xs[w][k];
        acc_a = fmaf(xv, Wrs[k * OUTD + lane], acc_a);
        acc_b = fmaf(xv, Wrs[k * OUTD + 32 + lane], acc_b);
    }
#pragma unroll
    for (int k = 0; k < D2; k++) {
        float m = Ms[w][k];
        acc_a = fmaf(m, Wls[k * OUTD + lane], acc_a);
        acc_b = fmaf(m, Wls[k * OUTD + 32 + lane], acc_b);
    }
    out[d * OUTD + lane]      = acc_a;
    out[d * OUTD + 32 + lane] = acc_b;
}

// ---------------- host ----------------
extern "C" void kernel_launch(void* const* d_in, const int* in_sizes, int n_in,
                              void* d_out, int out_size) {
    const float *x_prot = 0, *x_drug = 0, *W1 = 0, *b1 = 0, *W2 = 0, *b2 = 0;
    const float *Wl = 0, *bl = 0, *Wr = 0;
    const int *pp = 0, *pds = 0, *pdd = 0;
    int n200k = 0, n8192 = 0, n64 = 0, n2048 = 0;
    for (int i = 0; i < n_in; i++) {
        int s = in_sizes[i];
        void* p = d_in[i];
        if (s == NP * INP)        x_prot = (const float*)p;
        else if (s == ND * INP)   x_drug = (const float*)p;
        else if (s == 2 * EPP)    pp = (const int*)p;
        else if (s == EPD) {      if (n200k++ == 0) pds = (const int*)p; else pdd = (const int*)p; }
        else if (s == INP * D1) { if (n8192++ == 0) W1 = (const float*)p; else Wr = (const float*)p; }
        else if (s == D1) {       if (n64++   == 0) b1 = (const float*)p; else bl = (const float*)p; }
        else if (s == D1 * D2) {  if (n2048++ == 0) W2 = (const float*)p; else Wl = (const float*)p; }
        else if (s == D2)         b2 = (const float*)p;
    }
    const int4* pp_src4 = (const int4*)pp;
    const int4* pp_dst4 = (const int4*)(pp + EPP);
    float* h_out = (float*)d_out;                  // [NP, D2]
    float* drug_out = h_out + (long long)NP * D2;  // [ND, OUTD]

    __half* g_h1_p;  cudaGetSymbolAddress((void**)&g_h1_p, g_h1);
    __half* g_o1h_p; cudaGetSymbolAddress((void**)&g_o1h_p, g_o1h);
    __half* g_h2_p;  cudaGetSymbolAddress((void**)&g_h2_p, g_h2);

    static cudaStream_t s2 = 0;
    static cudaEvent_t evFork = 0, evJoin = 0;
    static int sideOk = -1;
    if (sideOk < 0) {
        sideOk = (cudaStreamCreateWithFlags(&s2, cudaStreamNonBlocking) == cudaSuccess &&
                  cudaEventCreateWithFlags(&evFork, cudaEventDisableTiming) == cudaSuccess &&
                  cudaEventCreateWithFlags(&evJoin, cudaEventDisableTiming) == cudaSuccess) ? 1 : 0;
    }

    if (sideOk) {
        cudaEventRecord(evFork, 0);
        cudaStreamWaitEvent(s2, evFork, 0);

        // side stream: fused CSR build (pp + pd)
        k_csr<<<CSRG, 256, 0, s2>>>(pp_src4, pp_dst4, pds, pdd);
        cudaEventRecord(evJoin, s2);

        // main stream: gemm1 overlaps CSR build
        k_gemm_h<INP, D1, 32><<<(NP + 63) / 64, 256>>>(x_prot, W1, g_h1_p, NP);
        cudaStreamWaitEvent(0, evJoin, 0);

        k_scale1<<<(NP * D1 / 16 + 255) / 256, 256>>>();
        k_gather64<<<(NP * 32 + 255) / 256, 256>>>(g_h1_p, b1, g_o1h_p);
        k_gemm2h<<<(NP + 127) / 128, 256>>>(g_o1h_p, W2, g_h2_p, NP);
        k_gather32<<<(NP * 32 + 255) / 256, 256>>>(g_h2_p, b2, h_out);
        k_drug<<<(ND + 7) / 8, 256>>>(h_out, x_drug, Wl, Wr, bl, drug_out);
    } else {
        k_csr<<<CSRG, 256>>>(pp_src4, pp_dst4, pds, pdd);
        k_gemm_h<INP, D1, 32><<<(NP + 63) / 64, 256>>>(x_prot, W1, g_h1_p, NP);
        k_scale1<<<(NP * D1 / 16 + 255) / 256, 256>>>();
        k_gather64<<<(NP * 32 + 255) / 256, 256>>>(g_h1_p, b1, g_o1h_p);
        k_gemm2h<<<(NP + 127) / 128, 256>>>(g_o1h_p, W2, g_h2_p, NP);
        k_gather32<<<(NP * 32 + 255) / 256, 256>>>(g_h2_p, b2, h_out);
        k_drug<<<(ND + 7) / 8, 256>>>(h_out, x_drug, Wl, Wr, bl, drug_out);
    }

    (void)out_size;
}

// round 14
// speedup vs baseline: 1.0560x; 1.0560x over previous
#include <cuda_runtime.h>
#include <cuda_fp16.h>

#define NP 50000          // N_PROT
#define ND 5000           // N_DRUG
#define EPP 1600000
#define EPD 200000
#define INP 128           // IN_PROT / IN_DRUG
#define D1 64
#define D2 32
#define OUTD 64

#define NB  196           // 256-wide scan blocks covering NP
#define NBD 20            // 256-wide scan blocks covering ND
#define CSRG 592          // fused CSR kernel grid (148 SMs x 4, co-resident)

// ---------------- scratch (device globals: no allocation allowed) ----------------
__device__ int      g_deg[NP];
__device__ float    g_dinv[NP];
__device__ int      g_bsum[NB];
__device__ int      g_boff[NB];
__device__ int      g_off[NP + 1];    // pp CSR row offsets (by dst protein)
__device__ int      g_pos[NP];
__device__ int      g_er[EPP];        // pp CSR: src index per slot (weights factored out)
__device__ int      g_degd[ND];
__device__ int      g_bsumd[NBD];
__device__ int      g_boffd[NBD];
__device__ int      g_offd[ND + 1];   // pd CSR row offsets (by drug)
__device__ int      g_posd[ND];
__device__ int      g_pdsrc[EPD];     // pd CSR: protein src per slot
__device__ __half   g_h1[NP * D1];    // x_prot @ W1, then scaled in-place: dinv*h1 (fp16)
__device__ __half   g_o1h[NP * D1];   // relu(propagated layer-1) (fp16)
__device__ __half   g_h2[NP * D2];    // dinv * (relu(o1) @ W2) (fp16)
__device__ float    g_xr[ND * OUTD];  // x_drug @ Wr + bl (precomputed off critical path)
__device__ unsigned g_barcnt = 0;
__device__ volatile unsigned g_bargen = 0;

// ---------------- helpers ----------------
__device__ __forceinline__ void grid_barrier() {
    __syncthreads();
    if (threadIdx.x == 0) {
        unsigned gen = g_bargen;
        __threadfence();
        unsigned t = atomicAdd(&g_barcnt, 1u);
        if (t == CSRG - 1) {
            g_barcnt = 0;
            __threadfence();
            g_bargen = gen + 1;
        } else {
            while (g_bargen == gen) __nanosleep(64);
        }
        __threadfence();
    }
    __syncthreads();
}

// ---------------- fused CSR build (pp by dst-protein AND pd by dst-drug) ----------------
__global__ void __launch_bounds__(256, 4)
k_csr(const int4* __restrict__ src4, const int4* __restrict__ dst4,
      const int* __restrict__ pds, const int* __restrict__ pdd) {
    __shared__ int sh[256];
    __shared__ int wsum[8];
    const int tid = threadIdx.x, b = blockIdx.x;
    const int gid = b * 256 + tid, gsz = CSRG * 256;

    // P0: zero degree arrays
    for (int i = gid; i < NP; i += gsz) g_deg[i] = 0;
    for (int i = gid; i < ND; i += gsz) g_degd[i] = 0;
    grid_barrier();

    // P1: degree histograms
    for (int i = gid; i < EPP / 4; i += gsz) {
        int4 d4 = dst4[i];
        atomicAdd(&g_deg[d4.x], 1); atomicAdd(&g_deg[d4.y], 1);
        atomicAdd(&g_deg[d4.z], 1); atomicAdd(&g_deg[d4.w], 1);
    }
    for (int i = gid; i < EPD; i += gsz) atomicAdd(&g_degd[pdd[i]], 1);
    grid_barrier();

    // P2: per-block sums (pp: blocks [0,NB); pd: blocks [NB, NB+NBD))
    if (b < NB) {
        int i = b * 256 + tid;
        int s = (i < NP) ? g_deg[i] : 0;
#pragma unroll
        for (int o = 16; o > 0; o >>= 1) s += __shfl_down_sync(0xffffffffu, s, o);
        if ((tid & 31) == 0) wsum[tid >> 5] = s;
        __syncthreads();
        if (tid < 8) {
            int w = wsum[tid];
#pragma unroll
            for (int o = 4; o > 0; o >>= 1) w += __shfl_down_sync(0xffu, w, o);
            if (tid == 0) g_bsum[b] = w;
        }
    } else if (b < NB + NBD) {
        int cb = b - NB;
        int i = cb * 256 + tid;
        int s = (i < ND) ? g_degd[i] : 0;
#pragma unroll
        for (int o = 16; o > 0; o >>= 1) s += __shfl_down_sync(0xffffffffu, s, o);
        if ((tid & 31) == 0) wsum[tid >> 5] = s;
        __syncthreads();
        if (tid < 8) {
            int w = wsum[tid];
#pragma unroll
            for (int o = 4; o > 0; o >>= 1) w += __shfl_down_sync(0xffu, w, o);
            if (tid == 0) g_bsumd[cb] = w;
        }
    }
    grid_barrier();

    // P3: block 0 scans pp partials; block 1 scans pd partials
    if (b == 0) {
        int v = (tid < NB) ? g_bsum[tid] : 0;
        sh[tid] = v;
        __syncthreads();
        for (int o = 1; o < 256; o <<= 1) {
            int u = (tid >= o) ? sh[tid - o] : 0;
            __syncthreads();
            sh[tid] += u;
            __syncthreads();
        }
        if (tid < NB) g_boff[tid] = sh[tid] - v;
    } else if (b == 1) {
        int v = (tid < NBD) ? g_bsumd[tid] : 0;
        sh[tid] = v;
        __syncthreads();
        for (int o = 1; o < 256; o <<= 1) {
            int u = (tid >= o) ? sh[tid - o] : 0;
            __syncthreads();
            sh[tid] += u;
            __syncthreads();
        }
        if (tid < NBD) g_boffd[tid] = sh[tid] - v;
    }
    grid_barrier();

    // P4: local exclusive scans
    if (b < NB) {
        int i = b * 256 + tid;
        int v = (i < NP) ? g_deg[i] : 0;
        sh[tid] = v;
        __syncthreads();
        for (int o = 1; o < 256; o <<= 1) {
            int u = (tid >= o) ? sh[tid - o] : 0;
            __syncthreads();
            sh[tid] += u;
            __syncthreads();
        }
        if (i < NP) {
            int off = g_boff[b] + sh[tid] - v;
            g_off[i] = off;
            g_pos[i] = off;
            g_dinv[i] = rsqrtf((float)v + 1.0f);   // +1 = self loop
        }
        if (i == NP - 1) g_off[NP] = EPP;
    } else if (b < NB + NBD) {
        int cb = b - NB;
        int i = cb * 256 + tid;
        int v = (i < ND) ? g_degd[i] : 0;
        sh[tid] = v;
        __syncthreads();
        for (int o = 1; o < 256; o <<= 1) {
            int u = (tid >= o) ? sh[tid - o] : 0;
            __syncthreads();
            sh[tid] += u;
            __syncthreads();
        }
        if (i < ND) {
            int off = g_boffd[cb] + sh[tid] - v;
            g_offd[i] = off;
            g_posd[i] = off;
        }
        if (i == ND - 1) g_offd[ND] = EPD;
    }
    grid_barrier();

    // P5: placement (counting sort); record = bare src index
    for (int i = gid; i < EPP / 4; i += gsz) {
        int4 s4 = src4[i];
        int4 d4 = dst4[i];
        { int p = atomicAdd(&g_pos[d4.x], 1); g_er[p] = s4.x; }
        { int p = atomicAdd(&g_pos[d4.y], 1); g_er[p] = s4.y; }
        { int p = atomicAdd(&g_pos[d4.z], 1); g_er[p] = s4.z; }
        { int p = atomicAdd(&g_pos[d4.w], 1); g_er[p] = s4.w; }
    }
    for (int i = gid; i < EPD; i += gsz) {
        int p = atomicAdd(&g_posd[pdd[i]], 1);
        g_pdsrc[p] = pds[i];
    }
}

// ---------------- GEMM1: Y = X @ W, fp32 in, fp16 out ----------------
template <int K, int M, int KC>
__global__ void __launch_bounds__(256)
k_gemm_h(const float* __restrict__ X, const float* __restrict__ W,
         __half* __restrict__ Y, int N) {
    constexpr int CG  = M / 4;
    constexpr int RG  = 256 / CG;
    constexpr int RPB = RG * 4;
    constexpr int KCP = KC + 2;
    __shared__ float Ws[K * M];
    __shared__ float Xs[RPB][KCP];

    const int tid = threadIdx.x;
    for (int i = tid; i < K * M; i += 256) Ws[i] = W[i];

    const int row0 = blockIdx.x * RPB;
    const int cg = tid % CG, rg = tid / CG;
    const int c0 = cg * 4, r0 = rg * 4;
    float acc[4][4];
#pragma unroll
    for (int j = 0; j < 4; j++)
#pragma unroll
        for (int i = 0; i < 4; i++) acc[j][i] = 0.f;

    for (int kc0 = 0; kc0 < K; kc0 += KC) {
        constexpr int NV = RPB * KC / 4;
#pragma unroll
        for (int v = 0; v < NV / 256; v++) {
            int idx = tid + v * 256;
            int r = idx / (KC / 4), kq = idx % (KC / 4);
            int gr = row0 + r;
            float4 x = make_float4(0.f, 0.f, 0.f, 0.f);
            if (gr < N) x = *(const float4*)&X[(long long)gr * K + kc0 + kq * 4];
            Xs[r][kq * 4 + 0] = x.x; Xs[r][kq * 4 + 1] = x.y;
            Xs[r][kq * 4 + 2] = x.z; Xs[r][kq * 4 + 3] = x.w;
        }
        __syncthreads();
#pragma unroll 4
        for (int k = 0; k < KC; k++) {
            float4 wb = *(const float4*)&Ws[(kc0 + k) * M + c0];
#pragma unroll
            for (int j = 0; j < 4; j++) {
                float xa = Xs[r0 + j][k];
                acc[j][0] = fmaf(xa, wb.x, acc[j][0]);
                acc[j][1] = fmaf(xa, wb.y, acc[j][1]);
                acc[j][2] = fmaf(xa, wb.z, acc[j][2]);
                acc[j][3] = fmaf(xa, wb.w, acc[j][3]);
            }
        }
        __syncthreads();
    }

#pragma unroll
    for (int j = 0; j < 4; j++) {
        int gr = row0 + r0 + j;
        if (gr < N) {
            __half2 p0 = __floats2half2_rn(acc[j][0], acc[j][1]);
            __half2 p1 = __floats2half2_rn(acc[j][2], acc[j][3]);
            uint2 pk;
            pk.x = *(unsigned int*)&p0;
            pk.y = *(unsigned int*)&p1;
            *(uint2*)(Y + (long long)gr * M + c0) = pk;
        }
    }
}

// ---------------- scale: g_h1 *= dinv[row] (in place, 16 halves/thread) ----------------
__global__ void __launch_bounds__(256)
k_scale1() {
    int t = blockIdx.x * blockDim.x + threadIdx.x;
    if (t >= NP * D1 / 16) return;          // 200000 threads
    float d = g_dinv[t >> 2];               // 4 threads per row, same dinv
    uint4* p = (uint4*)g_h1;
    uint4 a = p[2 * t], b = p[2 * t + 1];
    unsigned* va = (unsigned*)&a;
    unsigned* vb = (unsigned*)&b;
#pragma unroll
    for (int i = 0; i < 4; i++) {
        float2 fa = __half22float2(*(__half2*)&va[i]);
        float2 fb = __half22float2(*(__half2*)&vb[i]);
        __half2 ha = __floats2half2_rn(fa.x * d, fa.y * d);
        __half2 hb = __floats2half2_rn(fb.x * d, fb.y * d);
        va[i] = *(unsigned*)&ha;
        vb[i] = *(unsigned*)&hb;
    }
    p[2 * t] = a;
    p[2 * t + 1] = b;
}

// ---------------- GEMM2: Y = Xh @ W scaled by dinv, fp16 in/out ----------------
__global__ void __launch_bounds__(256)
k_gemm2h(const __half* __restrict__ Xh, const float* __restrict__ W,
         __half* __restrict__ Y, int N) {
    constexpr int K = D1, M = D2;
    constexpr int RPB = 128;
    __shared__ float Ws[K * M];
    __shared__ float Xs[RPB][K + 2];

    const int tid = threadIdx.x;
    for (int i = tid; i < K * M; i += 256) Ws[i] = W[i];

    const int row0 = blockIdx.x * RPB;
#pragma unroll
    for (int v = 0; v < 8; v++) {
        int idx = tid + v * 256;
        int r = idx / 16, kq = idx % 16;
        int gr = row0 + r;
        float4 xf = make_float4(0.f, 0.f, 0.f, 0.f);
        if (gr < N) {
            uint2 raw = *(const uint2*)(Xh + (long long)gr * K + kq * 4);
            float2 lo = __half22float2(*(__half2*)&raw.x);
            float2 hi = __half22float2(*(__half2*)&raw.y);
            xf = make_float4(lo.x, lo.y, hi.x, hi.y);
        }
        Xs[r][kq * 4 + 0] = xf.x; Xs[r][kq * 4 + 1] = xf.y;
        Xs[r][kq * 4 + 2] = xf.z; Xs[r][kq * 4 + 3] = xf.w;
    }
    __syncthreads();

    const int cg = tid % 8, rg = tid / 8;
    const int c0 = cg * 4, r0 = rg * 4;
    float acc[4][4];
#pragma unroll
    for (int j = 0; j < 4; j++)
#pragma unroll
        for (int i = 0; i < 4; i++) acc[j][i] = 0.f;
#pragma unroll 4
    for (int k = 0; k < K; k++) {
        float4 wb = *(const float4*)&Ws[k * M + c0];
#pragma unroll
        for (int j = 0; j < 4; j++) {
            float xa = Xs[r0 + j][k];
            acc[j][0] = fmaf(xa, wb.x, acc[j][0]);
            acc[j][1] = fmaf(xa, wb.y, acc[j][1]);
            acc[j][2] = fmaf(xa, wb.z, acc[j][2]);
            acc[j][3] = fmaf(xa, wb.w, acc[j][3]);
        }
    }
#pragma unroll
    for (int j = 0; j < 4; j++) {
        int gr = row0 + r0 + j;
        if (gr < N) {
            float d = g_dinv[gr];       // fuse dinv scaling (ht2 = dinv * h2)
            __half2 p0 = __floats2half2_rn(acc[j][0] * d, acc[j][1] * d);
            __half2 p1 = __floats2half2_rn(acc[j][2] * d, acc[j][3] * d);
            uint2 pk;
            pk.x = *(unsigned int*)&p0;
            pk.y = *(unsigned int*)&p1;
            *(uint2*)(Y + (long long)gr * M + c0) = pk;
        }
    }
}

// ---------------- gather layer1: warp/row, two 16-lane edge groups ----------------
// out[d] = relu(b1 + dinv[d] * (ht1[d] + sum_e ht1[src])), fp16 out
__global__ void __launch_bounds__(256)
k_gather64(const __half* __restrict__ ht, const float* __restrict__ b1,
           __half* __restrict__ out) {
    const int warp = (blockIdx.x * blockDim.x + threadIdx.x) >> 5;
    if (warp >= NP) return;
    const int lane = threadIdx.x & 31;
    const int g = lane >> 4, l = lane & 15;     // group, lane-in-group (4 cols each)
    const uint2* __restrict__ rows = (const uint2*)ht;   // row stride 16 uint2
    const int beg = g_off[warp], end = g_off[warp + 1];

    float a0 = 0.f, a1 = 0.f, a2 = 0.f, a3 = 0.f;
    int e = beg + g;
    for (; e + 2 < end; e += 4) {               // edges e, e+2 for this group
        int s0 = g_er[e], s1 = g_er[e + 2];
        uint2 r0 = rows[s0 * 16 + l];
        uint2 r1 = rows[s1 * 16 + l];
        float2 l0 = __half22float2(*(__half2*)&r0.x), h0 = __half22float2(*(__half2*)&r0.y);
        float2 l1 = __half22float2(*(__half2*)&r1.x), h1v = __half22float2(*(__half2*)&r1.y);
        a0 += l0.x + l1.x; a1 += l0.y + l1.y;
        a2 += h0.x + h1v.x; a3 += h0.y + h1v.y;
    }
    if (e < end) {
        uint2 r0 = rows[g_er[e] * 16 + l];
        float2 l0 = __half22float2(*(__half2*)&r0.x), h0 = __half22float2(*(__half2*)&r0.y);
        a0 += l0.x; a1 += l0.y; a2 += h0.x; a3 += h0.y;
    }
    if (g == 0) {   // self term once
        uint2 rs = rows[warp * 16 + l];
        float2 ls = __half22float2(*(__half2*)&rs.x), hs = __half22float2(*(__half2*)&rs.y);
        a0 += ls.x; a1 += ls.y; a2 += hs.x; a3 += hs.y;
    }
    // combine the two groups
    a0 += __shfl_xor_sync(0xffffffffu, a0, 16);
    a1 += __shfl_xor_sync(0xffffffffu, a1, 16);
    a2 += __shfl_xor_sync(0xffffffffu, a2, 16);
    a3 += __shfl_xor_sync(0xffffffffu, a3, 16);

    if (g == 0) {
        float d = g_dinv[warp];
        float4 bv = ((const float4*)b1)[l];
        float o0 = fmaxf(fmaf(d, a0, bv.x), 0.f);
        float o1 = fmaxf(fmaf(d, a1, bv.y), 0.f);
        float o2 = fmaxf(fmaf(d, a2, bv.z), 0.f);
        float o3 = fmaxf(fmaf(d, a3, bv.w), 0.f);
        __half2 p0 = __floats2half2_rn(o0, o1);
        __half2 p1 = __floats2half2_rn(o2, o3);
        uint2 pk;
        pk.x = *(unsigned*)&p0;
        pk.y = *(unsigned*)&p1;
        ((uint2*)out)[warp * 16 + l] = pk;
    }
}

// ---------------- gather layer2: warp/row, four 8-lane edge groups; fp32 out ----------------
// out[d] = b2 + dinv[d] * (ht2[d] + sum_e ht2[src])
__global__ void __launch_bounds__(256)
k_gather32(const __half* __restrict__ ht, const float* __restrict__ b2,
           float* __restrict__ out) {
    const int warp = (blockIdx.x * blockDim.x + threadIdx.x) >> 5;
    if (warp >= NP) return;
    const int lane = threadIdx.x & 31;
    const int g = lane >> 3, l = lane & 7;      // group 0..3, lane-in-group (4 cols)
    const uint2* __restrict__ rows = (const uint2*)ht;   // row stride 8 uint2
    const int beg = g_off[warp], end = g_off[warp + 1];

    float a0 = 0.f, a1 = 0.f, a2 = 0.f, a3 = 0.f;
    int e = beg + g;
    for (; e + 4 < end; e += 8) {               // edges e, e+4 for this group
        int s0 = g_er[e], s1 = g_er[e + 4];
        uint2 r0 = rows[s0 * 8 + l];
        uint2 r1 = rows[s1 * 8 + l];
        float2 l0 = __half22float2(*(__half2*)&r0.x), h0 = __half22float2(*(__half2*)&r0.y);
        float2 l1 = __half22float2(*(__half2*)&r1.x), h1v = __half22float2(*(__half2*)&r1.y);
        a0 += l0.x + l1.x; a1 += l0.y + l1.y;
        a2 += h0.x + h1v.x; a3 += h0.y + h1v.y;
    }
    if (e < end) {
        uint2 r0 = rows[g_er[e] * 8 + l];
        float2 l0 = __half22float2(*(__half2*)&r0.x), h0 = __half22float2(*(__half2*)&r0.y);
        a0 += l0.x; a1 += l0.y; a2 += h0.x; a3 += h0.y;
    }
    if (g == 0) {
        uint2 rs = rows[warp * 8 + l];
        float2 ls = __half22float2(*(__half2*)&rs.x), hs = __half22float2(*(__half2*)&rs.y);
        a0 += ls.x; a1 += ls.y; a2 += hs.x; a3 += hs.y;
    }
    // combine 4 groups
#pragma unroll
    for (int o = 8; o <= 16; o <<= 1) {
        a0 += __shfl_xor_sync(0xffffffffu, a0, o);
        a1 += __shfl_xor_sync(0xffffffffu, a1, o);
        a2 += __shfl_xor_sync(0xffffffffu, a2, o);
        a3 += __shfl_xor_sync(0xffffffffu, a3, o);
    }
    if (g == 0) {
        float d = g_dinv[warp];
        float4 bv = ((const float4*)b2)[l];
        float4 ov = make_float4(fmaf(d, a0, bv.x), fmaf(d, a1, bv.y),
                                fmaf(d, a2, bv.z), fmaf(d, a3, bv.w));
        ((float4*)out)[warp * 8 + l] = ov;
    }
}

// ---------------- precompute: g_xr = x_drug @ Wr + bl (off critical path) ----------------
__global__ void __launch_bounds__(256)
k_drug_xr(const float* __restrict__ xd, const float* __restrict__ Wr,
          const float* __restrict__ bl) {
    __shared__ float Wrs[INP * OUTD];   // 32KB
    __shared__ float Xs[4 * INP];
    const int tid = threadIdx.x;
    for (int i = tid; i < INP * OUTD; i += 256) Wrs[i] = Wr[i];
    const int row0 = blockIdx.x * 4;
    for (int i = tid; i < 4 * INP; i += 256)
        Xs[i] = xd[(row0 + i / INP) * INP + (i % INP)];
    __syncthreads();
    const int c = tid % OUTD;
    const int r = tid / OUTD;
    float acc = bl[c];
#pragma unroll 8
    for (int k = 0; k < INP; k++) acc = fmaf(Xs[r * INP + k], Wrs[k * OUTD + c], acc);
    g_xr[(row0 + r) * OUTD + c] = acc;
}

// ---------------- drug stage: gather-mean over pd CSR + @Wl + xr ----------------
__global__ void __launch_bounds__(256)
k_drug(const float* __restrict__ h, const float* __restrict__ Wl,
       float* __restrict__ out) {
    __shared__ float Wls[D2 * OUTD];   // 8KB
    __shared__ float Ms[8][D2];
    const int tid = threadIdx.x;
    for (int i = tid; i < D2 * OUTD; i += 256) Wls[i] = Wl[i];
    __syncthreads();

    const int w = tid >> 5, lane = tid & 31;
    const int d = blockIdx.x * 8 + w;
    if (d >= ND) return;
    const int beg = g_offd[d], end = g_offd[d + 1];

    float sum = 0.f;
    int e = beg;
    for (; e + 1 < end; e += 2) {
        int s0 = g_pdsrc[e], s1 = g_pdsrc[e + 1];
        sum += h[s0 * D2 + lane] + h[s1 * D2 + lane];
    }
    if (e < end) sum += h[g_pdsrc[e] * D2 + lane];
    float cnt = fmaxf((float)(end - beg), 1.0f);
    Ms[w][lane] = sum / cnt;
    __syncwarp();

    float acc_a = g_xr[d * OUTD + lane];
    float acc_b = g_xr[d * OUTD + 32 + lane];
#pragma unroll
    for (int k = 0; k < D2; k++) {
        float m = Ms[w][k];
        acc_a = fmaf(m, Wls[k * OUTD + lane], acc_a);
        acc_b = fmaf(m, Wls[k * OUTD + 32 + lane], acc_b);
    }
    out[d * OUTD + lane]      = acc_a;
    out[d * OUTD + 32 + lane] = acc_b;
}

// ---------------- host ----------------
extern "C" void kernel_launch(void* const* d_in, const int* in_sizes, int n_in,
                              void* d_out, int out_size) {
    const float *x_prot = 0, *x_drug = 0, *W1 = 0, *b1 = 0, *W2 = 0, *b2 = 0;
    const float *Wl = 0, *bl = 0, *Wr = 0;
    const int *pp = 0, *pds = 0, *pdd = 0;
    int n200k = 0, n8192 = 0, n64 = 0, n2048 = 0;
    for (int i = 0; i < n_in; i++) {
        int s = in_sizes[i];
        void* p = d_in[i];
        if (s == NP * INP)        x_prot = (const float*)p;
        else if (s == ND * INP)   x_drug = (const float*)p;
        else if (s == 2 * EPP)    pp = (const int*)p;
        else if (s == EPD) {      if (n200k++ == 0) pds = (const int*)p; else pdd = (const int*)p; }
        else if (s == INP * D1) { if (n8192++ == 0) W1 = (const float*)p; else Wr = (const float*)p; }
        else if (s == D1) {       if (n64++   == 0) b1 = (const float*)p; else bl = (const float*)p; }
        else if (s == D1 * D2) {  if (n2048++ == 0) W2 = (const float*)p; else Wl = (const float*)p; }
        else if (s == D2)         b2 = (const float*)p;
    }
    const int4* pp_src4 = (const int4*)pp;
    const int4* pp_dst4 = (const int4*)(pp + EPP);
    float* h_out = (float*)d_out;                  // [NP, D2]
    float* drug_out = h_out + (long long)NP * D2;  // [ND, OUTD]

    __half* g_h1_p;  cudaGetSymbolAddress((void**)&g_h1_p, g_h1);
    __half* g_o1h_p; cudaGetSymbolAddress((void**)&g_o1h_p, g_o1h);
    __half* g_h2_p;  cudaGetSymbolAddress((void**)&g_h2_p, g_h2);

    static cudaStream_t s2 = 0;
    static cudaEvent_t evFork = 0, evJoin = 0, evJoin2 = 0;
    static int sideOk = -1;
    if (sideOk < 0) {
        sideOk = (cudaStreamCreateWithFlags(&s2, cudaStreamNonBlocking) == cudaSuccess &&
                  cudaEventCreateWithFlags(&evFork, cudaEventDisableTiming) == cudaSuccess &&
                  cudaEventCreateWithFlags(&evJoin, cudaEventDisableTiming) == cudaSuccess &&
                  cudaEventCreateWithFlags(&evJoin2, cudaEventDisableTiming) == cudaSuccess) ? 1 : 0;
    }

    if (sideOk) {
        cudaEventRecord(evFork, 0);
        cudaStreamWaitEvent(s2, evFork, 0);

        // side stream: fused CSR build (pp + pd), then drug xr precompute
        k_csr<<<CSRG, 256, 0, s2>>>(pp_src4, pp_dst4, pds, pdd);
        cudaEventRecord(evJoin, s2);
        k_drug_xr<<<ND / 4, 256, 0, s2>>>(x_drug, Wr, bl);
        cudaEventRecord(evJoin2, s2);

        // main stream: gemm1 overlaps CSR build
        k_gemm_h<INP, D1, 32><<<(NP + 63) / 64, 256>>>(x_prot, W1, g_h1_p, NP);
        cudaStreamWaitEvent(0, evJoin, 0);

        k_scale1<<<(NP * D1 / 16 + 255) / 256, 256>>>();
        k_gather64<<<(NP * 32 + 255) / 256, 256>>>(g_h1_p, b1, g_o1h_p);
        k_gemm2h<<<(NP + 127) / 128, 256>>>(g_o1h_p, W2, g_h2_p, NP);
        k_gather32<<<(NP * 32 + 255) / 256, 256>>>(g_h2_p, b2, h_out);
        cudaStreamWaitEvent(0, evJoin2, 0);
        k_drug<<<(ND + 7) / 8, 256>>>(h_out, Wl, drug_out);
    } else {
        k_csr<<<CSRG, 256>>>(pp_src4, pp_dst4, pds, pdd);
        k_gemm_h<INP, D1, 32><<<(NP + 63) / 64, 256>>>(x_prot, W1, g_h1_p, NP);
        k_scale1<<<(NP * D1 / 16 + 255) / 256, 256>>>();
        k_gather64<<<(NP * 32 + 255) / 256, 256>>>(g_h1_p, b1, g_o1h_p);
        k_gemm2h<<<(NP + 127) / 128, 256>>>(g_o1h_p, W2, g_h2_p, NP);
        k_gather32<<<(NP * 32 + 255) / 256, 256>>>(g_h2_p, b2, h_out);
        k_drug_xr<<<ND / 4, 256>>>(x_drug, Wr, bl);
        k_drug<<<(ND + 7) / 8, 256>>>(h_out, Wl, drug_out);
    }

    (void)out_size;
}

// round 15
// speedup vs baseline: 1.0785x; 1.0213x over previous
#include <cuda_runtime.h>
#include <cuda_fp16.h>

#define NP 50000          // N_PROT
#define ND 5000           // N_DRUG
#define EPP 1600000
#define EPD 200000
#define INP 128           // IN_PROT / IN_DRUG
#define D1 64
#define D2 32
#define OUTD 64

#define NB  196           // 256-wide scan blocks covering NP
#define NBD 20            // 256-wide scan blocks covering ND
#define CSRG 592          // grid-barrier kernel grid (148 SMs x 4, co-resident)

// ---------------- scratch (device globals: no allocation allowed) ----------------
__device__ int      g_deg[NP];
__device__ float    g_dinv[NP];
__device__ int      g_bsum[NB];
__device__ int      g_boff[NB];
__device__ int      g_off[NP + 1];    // pp CSR row offsets (by dst protein)
__device__ int      g_pos[NP];
__device__ int      g_er[EPP];        // pp CSR: src index per slot (weights factored out)
__device__ int      g_degd[ND];
__device__ int      g_bsumd[NBD];
__device__ int      g_boffd[NBD];
__device__ int      g_offd[ND + 1];   // pd CSR row offsets (by drug)
__device__ int      g_posd[ND];
__device__ int      g_pdsrc[EPD];     // pd CSR: protein src per slot
__device__ __half   g_h1[NP * D1];    // ht1 = dinv * (x_prot @ W1)  (fp16, dinv fused in gemm1)
__device__ __half   g_o1h[NP * D1];   // relu(propagated layer-1) (fp16)
__device__ __half   g_h2[NP * D2];    // ht2 = dinv * (relu(o1) @ W2) (fp16)
__device__ float    g_xr[ND * OUTD];  // x_drug @ Wr + bl (precomputed off critical path)
__device__ unsigned g_barcnt = 0;
__device__ volatile unsigned g_bargen = 0;

// ---------------- helpers ----------------
__device__ __forceinline__ void grid_barrier() {
    __syncthreads();
    if (threadIdx.x == 0) {
        unsigned gen = g_bargen;
        __threadfence();
        unsigned t = atomicAdd(&g_barcnt, 1u);
        if (t == CSRG - 1) {
            g_barcnt = 0;
            __threadfence();
            g_bargen = gen + 1;
        } else {
            while (g_bargen == gen) __nanosleep(64);
        }
        __threadfence();
    }
    __syncthreads();
}

// ---------------- k_pre: zero -> degree histograms -> dinv (main stream) ----------------
__global__ void __launch_bounds__(256, 4)
k_pre(const int4* __restrict__ dst4, const int* __restrict__ pdd) {
    const int tid = threadIdx.x, b = blockIdx.x;
    const int gid = b * 256 + tid, gsz = CSRG * 256;

    for (int i = gid; i < NP; i += gsz) g_deg[i] = 0;
    for (int i = gid; i < ND; i += gsz) g_degd[i] = 0;
    grid_barrier();

    for (int i = gid; i < EPP / 4; i += gsz) {
        int4 d4 = dst4[i];
        atomicAdd(&g_deg[d4.x], 1); atomicAdd(&g_deg[d4.y], 1);
        atomicAdd(&g_deg[d4.z], 1); atomicAdd(&g_deg[d4.w], 1);
    }
    for (int i = gid; i < EPD; i += gsz) atomicAdd(&g_degd[pdd[i]], 1);
    grid_barrier();

    for (int i = gid; i < NP; i += gsz)
        g_dinv[i] = rsqrtf((float)g_deg[i] + 1.0f);   // +1 = self loop
}

// ---------------- k_mid: scans -> offsets -> placement (side stream) ----------------
__global__ void __launch_bounds__(256, 4)
k_mid(const int4* __restrict__ src4, const int4* __restrict__ dst4,
      const int* __restrict__ pds, const int* __restrict__ pdd) {
    __shared__ int sh[256];
    __shared__ int wsum[8];
    const int tid = threadIdx.x, b = blockIdx.x;
    const int gid = b * 256 + tid, gsz = CSRG * 256;

    // P2: per-block sums (pp: blocks [0,NB); pd: blocks [NB, NB+NBD))
    if (b < NB) {
        int i = b * 256 + tid;
        int s = (i < NP) ? g_deg[i] : 0;
#pragma unroll
        for (int o = 16; o > 0; o >>= 1) s += __shfl_down_sync(0xffffffffu, s, o);
        if ((tid & 31) == 0) wsum[tid >> 5] = s;
        __syncthreads();
        if (tid < 8) {
            int w = wsum[tid];
#pragma unroll
            for (int o = 4; o > 0; o >>= 1) w += __shfl_down_sync(0xffu, w, o);
            if (tid == 0) g_bsum[b] = w;
        }
    } else if (b < NB + NBD) {
        int cb = b - NB;
        int i = cb * 256 + tid;
        int s = (i < ND) ? g_degd[i] : 0;
#pragma unroll
        for (int o = 16; o > 0; o >>= 1) s += __shfl_down_sync(0xffffffffu, s, o);
        if ((tid & 31) == 0) wsum[tid >> 5] = s;
        __syncthreads();
        if (tid < 8) {
            int w = wsum[tid];
#pragma unroll
            for (int o = 4; o > 0; o >>= 1) w += __shfl_down_sync(0xffu, w, o);
            if (tid == 0) g_bsumd[cb] = w;
        }
    }
    grid_barrier();

    // P3: block 0 scans pp partials; block 1 scans pd partials
    if (b == 0) {
        int v = (tid < NB) ? g_bsum[tid] : 0;
        sh[tid] = v;
        __syncthreads();
        for (int o = 1; o < 256; o <<= 1) {
            int u = (tid >= o) ? sh[tid - o] : 0;
            __syncthreads();
            sh[tid] += u;
            __syncthreads();
        }
        if (tid < NB) g_boff[tid] = sh[tid] - v;
    } else if (b == 1) {
        int v = (tid < NBD) ? g_bsumd[tid] : 0;
        sh[tid] = v;
        __syncthreads();
        for (int o = 1; o < 256; o <<= 1) {
            int u = (tid >= o) ? sh[tid - o] : 0;
            __syncthreads();
            sh[tid] += u;
            __syncthreads();
        }
        if (tid < NBD) g_boffd[tid] = sh[tid] - v;
    }
    grid_barrier();

    // P4: local exclusive scans -> offsets + cursors
    if (b < NB) {
        int i = b * 256 + tid;
        int v = (i < NP) ? g_deg[i] : 0;
        sh[tid] = v;
        __syncthreads();
        for (int o = 1; o < 256; o <<= 1) {
            int u = (tid >= o) ? sh[tid - o] : 0;
            __syncthreads();
            sh[tid] += u;
            __syncthreads();
        }
        if (i < NP) {
            int off = g_boff[b] + sh[tid] - v;
            g_off[i] = off;
            g_pos[i] = off;
        }
        if (i == NP - 1) g_off[NP] = EPP;
    } else if (b < NB + NBD) {
        int cb = b - NB;
        int i = cb * 256 + tid;
        int v = (i < ND) ? g_degd[i] : 0;
        sh[tid] = v;
        __syncthreads();
        for (int o = 1; o < 256; o <<= 1) {
            int u = (tid >= o) ? sh[tid - o] : 0;
            __syncthreads();
            sh[tid] += u;
            __syncthreads();
        }
        if (i < ND) {
            int off = g_boffd[cb] + sh[tid] - v;
            g_offd[i] = off;
            g_posd[i] = off;
        }
        if (i == ND - 1) g_offd[ND] = EPD;
    }
    grid_barrier();

    // P5: placement (counting sort); record = bare src index
    for (int i = gid; i < EPP / 4; i += gsz) {
        int4 s4 = src4[i];
        int4 d4 = dst4[i];
        { int p = atomicAdd(&g_pos[d4.x], 1); g_er[p] = s4.x; }
        { int p = atomicAdd(&g_pos[d4.y], 1); g_er[p] = s4.y; }
        { int p = atomicAdd(&g_pos[d4.z], 1); g_er[p] = s4.z; }
        { int p = atomicAdd(&g_pos[d4.w], 1); g_er[p] = s4.w; }
    }
    for (int i = gid; i < EPD; i += gsz) {
        int p = atomicAdd(&g_posd[pdd[i]], 1);
        g_pdsrc[p] = pds[i];
    }
}

// ---------------- GEMM1: Y = dinv * (X @ W), fp32 in, fp16 out (dinv fused) ----------------
template <int K, int M, int KC>
__global__ void __launch_bounds__(256)
k_gemm_h(const float* __restrict__ X, const float* __restrict__ W,
         __half* __restrict__ Y, int N) {
    constexpr int CG  = M / 4;
    constexpr int RG  = 256 / CG;
    constexpr int RPB = RG * 4;
    constexpr int KCP = KC + 2;
    __shared__ float Ws[K * M];
    __shared__ float Xs[RPB][KCP];

    const int tid = threadIdx.x;
    for (int i = tid; i < K * M; i += 256) Ws[i] = W[i];

    const int row0 = blockIdx.x * RPB;
    const int cg = tid % CG, rg = tid / CG;
    const int c0 = cg * 4, r0 = rg * 4;
    float acc[4][4];
#pragma unroll
    for (int j = 0; j < 4; j++)
#pragma unroll
        for (int i = 0; i < 4; i++) acc[j][i] = 0.f;

    for (int kc0 = 0; kc0 < K; kc0 += KC) {
        constexpr int NV = RPB * KC / 4;
#pragma unroll
        for (int v = 0; v < NV / 256; v++) {
            int idx = tid + v * 256;
            int r = idx / (KC / 4), kq = idx % (KC / 4);
            int gr = row0 + r;
            float4 x = make_float4(0.f, 0.f, 0.f, 0.f);
            if (gr < N) x = *(const float4*)&X[(long long)gr * K + kc0 + kq * 4];
            Xs[r][kq * 4 + 0] = x.x; Xs[r][kq * 4 + 1] = x.y;
            Xs[r][kq * 4 + 2] = x.z; Xs[r][kq * 4 + 3] = x.w;
        }
        __syncthreads();
#pragma unroll 4
        for (int k = 0; k < KC; k++) {
            float4 wb = *(const float4*)&Ws[(kc0 + k) * M + c0];
#pragma unroll
            for (int j = 0; j < 4; j++) {
                float xa = Xs[r0 + j][k];
                acc[j][0] = fmaf(xa, wb.x, acc[j][0]);
                acc[j][1] = fmaf(xa, wb.y, acc[j][1]);
                acc[j][2] = fmaf(xa, wb.z, acc[j][2]);
                acc[j][3] = fmaf(xa, wb.w, acc[j][3]);
            }
        }
        __syncthreads();
    }

#pragma unroll
    for (int j = 0; j < 4; j++) {
        int gr = row0 + r0 + j;
        if (gr < N) {
            float d = g_dinv[gr];   // fused: ht1 = dinv * (x @ W1)
            __half2 p0 = __floats2half2_rn(acc[j][0] * d, acc[j][1] * d);
            __half2 p1 = __floats2half2_rn(acc[j][2] * d, acc[j][3] * d);
            uint2 pk;
            pk.x = *(unsigned int*)&p0;
            pk.y = *(unsigned int*)&p1;
            *(uint2*)(Y + (long long)gr * M + c0) = pk;
        }
    }
}

// ---------------- GEMM2: Y = dinv * (Xh @ W), fp16 in/out ----------------
__global__ void __launch_bounds__(256)
k_gemm2h(const __half* __restrict__ Xh, const float* __restrict__ W,
         __half* __restrict__ Y, int N) {
    constexpr int K = D1, M = D2;
    constexpr int RPB = 128;
    __shared__ float Ws[K * M];
    __shared__ float Xs[RPB][K + 2];

    const int tid = threadIdx.x;
    for (int i = tid; i < K * M; i += 256) Ws[i] = W[i];

    const int row0 = blockIdx.x * RPB;
#pragma unroll
    for (int v = 0; v < 8; v++) {
        int idx = tid + v * 256;
        int r = idx / 16, kq = idx % 16;
        int gr = row0 + r;
        float4 xf = make_float4(0.f, 0.f, 0.f, 0.f);
        if (gr < N) {
            uint2 raw = *(const uint2*)(Xh + (long long)gr * K + kq * 4);
            float2 lo = __half22float2(*(__half2*)&raw.x);
            float2 hi = __half22float2(*(__half2*)&raw.y);
            xf = make_float4(lo.x, lo.y, hi.x, hi.y);
        }
        Xs[r][kq * 4 + 0] = xf.x; Xs[r][kq * 4 + 1] = xf.y;
        Xs[r][kq * 4 + 2] = xf.z; Xs[r][kq * 4 + 3] = xf.w;
    }
    __syncthreads();

    const int cg = tid % 8, rg = tid / 8;
    const int c0 = cg * 4, r0 = rg * 4;
    float acc[4][4];
#pragma unroll
    for (int j = 0; j < 4; j++)
#pragma unroll
        for (int i = 0; i < 4; i++) acc[j][i] = 0.f;
#pragma unroll 4
    for (int k = 0; k < K; k++) {
        float4 wb = *(const float4*)&Ws[k * M + c0];
#pragma unroll
        for (int j = 0; j < 4; j++) {
            float xa = Xs[r0 + j][k];
            acc[j][0] = fmaf(xa, wb.x, acc[j][0]);
            acc[j][1] = fmaf(xa, wb.y, acc[j][1]);
            acc[j][2] = fmaf(xa, wb.z, acc[j][2]);
            acc[j][3] = fmaf(xa, wb.w, acc[j][3]);
        }
    }
#pragma unroll
    for (int j = 0; j < 4; j++) {
        int gr = row0 + r0 + j;
        if (gr < N) {
            float d = g_dinv[gr];       // fuse dinv scaling (ht2 = dinv * h2)
            __half2 p0 = __floats2half2_rn(acc[j][0] * d, acc[j][1] * d);
            __half2 p1 = __floats2half2_rn(acc[j][2] * d, acc[j][3] * d);
            uint2 pk;
            pk.x = *(unsigned int*)&p0;
            pk.y = *(unsigned int*)&p1;
            *(uint2*)(Y + (long long)gr * M + c0) = pk;
        }
    }
}

// ---------------- gather layer1: warp/row, two 16-lane edge groups ----------------
// out[d] = relu(b1 + dinv[d] * (ht1[d] + sum_e ht1[src])), fp16 out
__global__ void __launch_bounds__(256)
k_gather64(const __half* __restrict__ ht, const float* __restrict__ b1,
           __half* __restrict__ out) {
    const int warp = (blockIdx.x * blockDim.x + threadIdx.x) >> 5;
    if (warp >= NP) return;
    const int lane = threadIdx.x & 31;
    const int g = lane >> 4, l = lane & 15;     // group, lane-in-group (4 cols each)
    const uint2* __restrict__ rows = (const uint2*)ht;   // row stride 16 uint2
    const int beg = g_off[warp], end = g_off[warp + 1];

    float a0 = 0.f, a1 = 0.f, a2 = 0.f, a3 = 0.f;
    int e = beg + g;
    for (; e + 2 < end; e += 4) {               // edges e, e+2 for this group
        int s0 = g_er[e], s1 = g_er[e + 2];
        uint2 r0 = rows[s0 * 16 + l];
        uint2 r1 = rows[s1 * 16 + l];
        float2 l0 = __half22float2(*(__half2*)&r0.x), h0 = __half22float2(*(__half2*)&r0.y);
        float2 l1 = __half22float2(*(__half2*)&r1.x), h1v = __half22float2(*(__half2*)&r1.y);
        a0 += l0.x + l1.x; a1 += l0.y + l1.y;
        a2 += h0.x + h1v.x; a3 += h0.y + h1v.y;
    }
    if (e < end) {
        uint2 r0 = rows[g_er[e] * 16 + l];
        float2 l0 = __half22float2(*(__half2*)&r0.x), h0 = __half22float2(*(__half2*)&r0.y);
        a0 += l0.x; a1 += l0.y; a2 += h0.x; a3 += h0.y;
    }
    if (g == 0) {   // self term once
        uint2 rs = rows[warp * 16 + l];
        float2 ls = __half22float2(*(__half2*)&rs.x), hs = __half22float2(*(__half2*)&rs.y);
        a0 += ls.x; a1 += ls.y; a2 += hs.x; a3 += hs.y;
    }
    // combine the two groups
    a0 += __shfl_xor_sync(0xffffffffu, a0, 16);
    a1 += __shfl_xor_sync(0xffffffffu, a1, 16);
    a2 += __shfl_xor_sync(0xffffffffu, a2, 16);
    a3 += __shfl_xor_sync(0xffffffffu, a3, 16);

    if (g == 0) {
        float d = g_dinv[warp];
        float4 bv = ((const float4*)b1)[l];
        float o0 = fmaxf(fmaf(d, a0, bv.x), 0.f);
        float o1 = fmaxf(fmaf(d, a1, bv.y), 0.f);
        float o2 = fmaxf(fmaf(d, a2, bv.z), 0.f);
        float o3 = fmaxf(fmaf(d, a3, bv.w), 0.f);
        __half2 p0 = __floats2half2_rn(o0, o1);
        __half2 p1 = __floats2half2_rn(o2, o3);
        uint2 pk;
        pk.x = *(unsigned*)&p0;
        pk.y = *(unsigned*)&p1;
        ((uint2*)out)[warp * 16 + l] = pk;
    }
}

// ---------------- gather layer2: warp/row, four 8-lane edge groups; fp32 out ----------------
// out[d] = b2 + dinv[d] * (ht2[d] + sum_e ht2[src])
__global__ void __launch_bounds__(256)
k_gather32(const __half* __restrict__ ht, const float* __restrict__ b2,
           float* __restrict__ out) {
    const int warp = (blockIdx.x * blockDim.x + threadIdx.x) >> 5;
    if (warp >= NP) return;
    const int lane = threadIdx.x & 31;
    const int g = lane >> 3, l = lane & 7;      // group 0..3, lane-in-group (4 cols)
    const uint2* __restrict__ rows = (const uint2*)ht;   // row stride 8 uint2
    const int beg = g_off[warp], end = g_off[warp + 1];

    float a0 = 0.f, a1 = 0.f, a2 = 0.f, a3 = 0.f;
    int e = beg + g;
    for (; e + 4 < end; e += 8) {               // edges e, e+4 for this group
        int s0 = g_er[e], s1 = g_er[e + 4];
        uint2 r0 = rows[s0 * 8 + l];
        uint2 r1 = rows[s1 * 8 + l];
        float2 l0 = __half22float2(*(__half2*)&r0.x), h0 = __half22float2(*(__half2*)&r0.y);
        float2 l1 = __half22float2(*(__half2*)&r1.x), h1v = __half22float2(*(__half2*)&r1.y);
        a0 += l0.x + l1.x; a1 += l0.y + l1.y;
        a2 += h0.x + h1v.x; a3 += h0.y + h1v.y;
    }
    if (e < end) {
        uint2 r0 = rows[g_er[e] * 8 + l];
        float2 l0 = __half22float2(*(__half2*)&r0.x), h0 = __half22float2(*(__half2*)&r0.y);
        a0 += l0.x; a1 += l0.y; a2 += h0.x; a3 += h0.y;
    }
    if (g == 0) {
        uint2 rs = rows[warp * 8 + l];
        float2 ls = __half22float2(*(__half2*)&rs.x), hs = __half22float2(*(__half2*)&rs.y);
        a0 += ls.x; a1 += ls.y; a2 += hs.x; a3 += hs.y;
    }
    // combine 4 groups
#pragma unroll
    for (int o = 8; o <= 16; o <<= 1) {
        a0 += __shfl_xor_sync(0xffffffffu, a0, o);
        a1 += __shfl_xor_sync(0xffffffffu, a1, o);
        a2 += __shfl_xor_sync(0xffffffffu, a2, o);
        a3 += __shfl_xor_sync(0xffffffffu, a3, o);
    }
    if (g == 0) {
        float d = g_dinv[warp];
        float4 bv = ((const float4*)b2)[l];
        float4 ov = make_float4(fmaf(d, a0, bv.x), fmaf(d, a1, bv.y),
                                fmaf(d, a2, bv.z), fmaf(d, a3, bv.w));
        ((float4*)out)[warp * 8 + l] = ov;
    }
}

// ---------------- precompute: g_xr = x_drug @ Wr + bl (off critical path) ----------------
__global__ void __launch_bounds__(256)
k_drug_xr(const float* __restrict__ xd, const float* __restrict__ Wr,
          const float* __restrict__ bl) {
    __shared__ float Wrs[INP * OUTD];   // 32KB
    __shared__ float Xs[4 * INP];
    const int tid = threadIdx.x;
    for (int i = tid; i < INP * OUTD; i += 256) Wrs[i] = Wr[i];
    const int row0 = blockIdx.x * 4;
    for (int i = tid; i < 4 * INP; i += 256)
        Xs[i] = xd[(row0 + i / INP) * INP + (i % INP)];
    __syncthreads();
    const int c = tid % OUTD;
    const int r = tid / OUTD;
    float acc = bl[c];
#pragma unroll 8
    for (int k = 0; k < INP; k++) acc = fmaf(Xs[r * INP + k], Wrs[k * OUTD + c], acc);
    g_xr[(row0 + r) * OUTD + c] = acc;
}

// ---------------- drug stage: gather-mean over pd CSR + @Wl + xr ----------------
__global__ void __launch_bounds__(256)
k_drug(const float* __restrict__ h, const float* __restrict__ Wl,
       float* __restrict__ out) {
    __shared__ float Wls[D2 * OUTD];   // 8KB
    __shared__ float Ms[8][D2];
    const int tid = threadIdx.x;
    for (int i = tid; i < D2 * OUTD; i += 256) Wls[i] = Wl[i];
    __syncthreads();

    const int w = tid >> 5, lane = tid & 31;
    const int d = blockIdx.x * 8 + w;
    if (d >= ND) return;
    const int beg = g_offd[d], end = g_offd[d + 1];

    float sum = 0.f;
    int e = beg;
    for (; e + 1 < end; e += 2) {
        int s0 = g_pdsrc[e], s1 = g_pdsrc[e + 1];
        sum += h[s0 * D2 + lane] + h[s1 * D2 + lane];
    }
    if (e < end) sum += h[g_pdsrc[e] * D2 + lane];
    float cnt = fmaxf((float)(end - beg), 1.0f);
    Ms[w][lane] = sum / cnt;
    __syncwarp();

    float acc_a = g_xr[d * OUTD + lane];
    float acc_b = g_xr[d * OUTD + 32 + lane];
#pragma unroll
    for (int k = 0; k < D2; k++) {
        float m = Ms[w][k];
        acc_a = fmaf(m, Wls[k * OUTD + lane], acc_a);
        acc_b = fmaf(m, Wls[k * OUTD + 32 + lane], acc_b);
    }
    out[d * OUTD + lane]      = acc_a;
    out[d * OUTD + 32 + lane] = acc_b;
}

// ---------------- host ----------------
extern "C" void kernel_launch(void* const* d_in, const int* in_sizes, int n_in,
                              void* d_out, int out_size) {
    const float *x_prot = 0, *x_drug = 0, *W1 = 0, *b1 = 0, *W2 = 0, *b2 = 0;
    const float *Wl = 0, *bl = 0, *Wr = 0;
    const int *pp = 0, *pds = 0, *pdd = 0;
    int n200k = 0, n8192 = 0, n64 = 0, n2048 = 0;
    for (int i = 0; i < n_in; i++) {
        int s = in_sizes[i];
        void* p = d_in[i];
        if (s == NP * INP)        x_prot = (const float*)p;
        else if (s == ND * INP)   x_drug = (const float*)p;
        else if (s == 2 * EPP)    pp = (const int*)p;
        else if (s == EPD) {      if (n200k++ == 0) pds = (const int*)p; else pdd = (const int*)p; }
        else if (s == INP * D1) { if (n8192++ == 0) W1 = (const float*)p; else Wr = (const float*)p; }
        else if (s == D1) {       if (n64++   == 0) b1 = (const float*)p; else bl = (const float*)p; }
        else if (s == D1 * D2) {  if (n2048++ == 0) W2 = (const float*)p; else Wl = (const float*)p; }
        else if (s == D2)         b2 = (const float*)p;
    }
    const int4* pp_src4 = (const int4*)pp;
    const int4* pp_dst4 = (const int4*)(pp + EPP);
    float* h_out = (float*)d_out;                  // [NP, D2]
    float* drug_out = h_out + (long long)NP * D2;  // [ND, OUTD]

    __half* g_h1_p;  cudaGetSymbolAddress((void**)&g_h1_p, g_h1);
    __half* g_o1h_p; cudaGetSymbolAddress((void**)&g_o1h_p, g_o1h);
    __half* g_h2_p;  cudaGetSymbolAddress((void**)&g_h2_p, g_h2);

    static cudaStream_t s2 = 0;
    static cudaEvent_t evFork = 0, evJoin = 0, evJoin2 = 0;
    static int sideOk = -1;
    if (sideOk < 0) {
        sideOk = (cudaStreamCreateWithFlags(&s2, cudaStreamNonBlocking) == cudaSuccess &&
                  cudaEventCreateWithFlags(&evFork, cudaEventDisableTiming) == cudaSuccess &&
                  cudaEventCreateWithFlags(&evJoin, cudaEventDisableTiming) == cudaSuccess &&
                  cudaEventCreateWithFlags(&evJoin2, cudaEventDisableTiming) == cudaSuccess) ? 1 : 0;
    }

    if (sideOk) {
        // main: degrees + dinv first (gemm1 epilogue needs dinv)
        k_pre<<<CSRG, 256>>>(pp_dst4, pdd);
        cudaEventRecord(evFork, 0);
        cudaStreamWaitEvent(s2, evFork, 0);

        // side: scans + placement, then drug xr precompute
        k_mid<<<CSRG, 256, 0, s2>>>(pp_src4, pp_dst4, pds, pdd);
        cudaEventRecord(evJoin, s2);
        k_drug_xr<<<ND / 4, 256, 0, s2>>>(x_drug, Wr, bl);
        cudaEventRecord(evJoin2, s2);

        // main: gemm1 (dinv fused) overlaps k_mid
        k_gemm_h<INP, D1, 32><<<(NP + 63) / 64, 256>>>(x_prot, W1, g_h1_p, NP);
        cudaStreamWaitEvent(0, evJoin, 0);

        k_gather64<<<(NP * 32 + 255) / 256, 256>>>(g_h1_p, b1, g_o1h_p);
        k_gemm2h<<<(NP + 127) / 128, 256>>>(g_o1h_p, W2, g_h2_p, NP);
        k_gather32<<<(NP * 32 + 255) / 256, 256>>>(g_h2_p, b2, h_out);
        cudaStreamWaitEvent(0, evJoin2, 0);
        k_drug<<<(ND + 7) / 8, 256>>>(h_out, Wl, drug_out);
    } else {
        k_pre<<<CSRG, 256>>>(pp_dst4, pdd);
        k_mid<<<CSRG, 256>>>(pp_src4, pp_dst4, pds, pdd);
        k_gemm_h<INP, D1, 32><<<(NP + 63) / 64, 256>>>(x_prot, W1, g_h1_p, NP);
        k_gather64<<<(NP * 32 + 255) / 256, 256>>>(g_h1_p, b1, g_o1h_p);
        k_gemm2h<<<(NP + 127) / 128, 256>>>(g_o1h_p, W2, g_h2_p, NP);
        k_gather32<<<(NP * 32 + 255) / 256, 256>>>(g_h2_p, b2, h_out);
        k_drug_xr<<<ND / 4, 256>>>(x_drug, Wr, bl);
        k_drug<<<(ND + 7) / 8, 256>>>(h_out, Wl, drug_out);
    }

    (void)out_size;
}